// round 16
// baseline (speedup 1.0000x reference)
#include <cuda_runtime.h>
#include <math.h>
#include <stdint.h>

#define TB_E      64
#define NTHREADS  256
#define WN        2560
#define NCHUNKS   20

typedef unsigned long long u64;

// ---------------- compile-time path tables ----------------
constexpr int   H_MID_DJ[6]  = {1,3,3,1,3,5};
constexpr int   H_T1_I1[6] = {0,0,1,1,1,1};
constexpr int   H_T1_I2[6] = {0,1,0,1,1,1};
constexpr int   H_T1_CG[6] = {0,1,10,19,28,55};
constexpr float H_T1_PW[6] = {1.f,1.7320508075688772f,1.7320508075688772f,1.f,
                              1.7320508075688772f,2.2360679774997896f};
#define S1c 0.08838834764831845f /* sqrt(3/384) */
constexpr int   HP_I1[10] = {0,0,0,0,1,1,1,1,1,1};
constexpr int   HP_I2[10] = {0,1,2,3,0,1,2,3,4,5};
constexpr int   HP_IO[10] = {0,1,1,0,1,0,0,1,1,1};
constexpr int   HP_CG[10] = {0,1,1,0,10,19,19,10,28,100};
constexpr float HP_PW[10] = {0.0625f,S1c,S1c,0.0625f,S1c,0.0625f,0.0625f,S1c,S1c,S1c};

// CG table layout: [0]=C000(1), [1..9]=C011, [10..18]=C101, [19..27]=C110,
//                  [28..54]=C111, [55..99]=C112, [100..144]=C121
struct ConvConsts {
    float cg[160];
    float silu_c;
};

// pre-packed W1: col-major [n][kp-interleaved], u64 = (bf16x2 hi, bf16x2 lo)
__device__ u64 g_W1p[WN*32];

// ---------------- helpers ----------------
__device__ __forceinline__ u64 pk2(float lo, float hi){ u64 r; asm("mov.b64 %0,{%1,%2};" : "=l"(r) : "f"(lo), "f"(hi)); return r; }
__device__ __forceinline__ u64 dup2(float x){ u64 r; asm("mov.b64 %0,{%1,%1};" : "=l"(r) : "f"(x)); return r; }
__device__ __forceinline__ u64 mul2(u64 a, u64 b){ u64 r; asm("mul.rn.f32x2 %0,%1,%2;" : "=l"(r) : "l"(a), "l"(b)); return r; }
__device__ __forceinline__ void fma2(u64 &d, u64 a, u64 b){ asm("fma.rn.f32x2 %0,%1,%2,%0;" : "+l"(d) : "l"(a), "l"(b)); }
__device__ __forceinline__ u64 add2(u64 a, u64 b){ u64 r; asm("add.rn.f32x2 %0,%1,%2;" : "=l"(r) : "l"(a), "l"(b)); return r; }
__device__ __forceinline__ void upk2(u64 v, float &lo, float &hi){ asm("mov.b64 {%0,%1},%2;" : "=f"(lo), "=f"(hi) : "l"(v)); }
__device__ __forceinline__ void upku(u64 v, uint32_t &lo, uint32_t &hi){ asm("mov.b64 {%0,%1},%2;" : "=r"(lo), "=r"(hi) : "l"(v)); }
__device__ __forceinline__ u64 pku(uint32_t lo, uint32_t hi){ u64 r; asm("mov.b64 %0,{%1,%2};" : "=l"(r) : "r"(lo), "r"(hi)); return r; }

__device__ __forceinline__ void cpasync16(void* dst_smem, const void* src_gmem){
    uint32_t d = (uint32_t)__cvta_generic_to_shared(dst_smem);
    asm volatile("cp.async.cg.shared.global [%0], [%1], 16;" :: "r"(d), "l"(src_gmem) : "memory");
}
__device__ __forceinline__ void cpasync_commit(){ asm volatile("cp.async.commit_group;" ::: "memory"); }
__device__ __forceinline__ void cpasync_wait0(){ asm volatile("cp.async.wait_group 0;" ::: "memory"); }

// pack: low 16 = bf16(f0), high 16 = bf16(f1)
__device__ __forceinline__ uint32_t packbf(float f0, float f1){
    uint32_t r; asm("cvt.rn.bf16x2.f32 %0,%1,%2;" : "=r"(r) : "f"(f1), "f"(f0)); return r;
}
// split two floats into (hi-pair, lo-pair) u64
__device__ __forceinline__ u64 split_pair(float f0, float f1){
    uint32_t hp = packbf(f0, f1);
    float h0 = __uint_as_float(hp << 16);
    float h1 = __uint_as_float(hp & 0xFFFF0000u);
    uint32_t lp = packbf(f0 - h0, f1 - h1);
    return pku(hp, lp);
}

__device__ __forceinline__ void mma_bf16(float (&c)[4],
    uint32_t a0, uint32_t a1, uint32_t a2, uint32_t a3, uint32_t b0, uint32_t b1)
{
    asm("mma.sync.aligned.m16n8k16.row.col.f32.bf16.bf16.f32 "
        "{%0,%1,%2,%3},{%4,%5,%6,%7},{%8,%9},{%0,%1,%2,%3};"
        : "+f"(c[0]),"+f"(c[1]),"+f"(c[2]),"+f"(c[3])
        : "r"(a0),"r"(a1),"r"(a2),"r"(a3),"r"(b0),"r"(b1));
}

// ---------------- host-side CG computation (reference transliteration) ----------------
struct CxH { double re, im; };
static CxH cxmulH(CxH a, CxH b){ CxH r; r.re=a.re*b.re-a.im*b.im; r.im=a.re*b.im+a.im*b.re; return r; }
static double dfactH(int n){ double r=1.0; for(int i=2;i<=n;i++) r*=(double)i; return r; }

static void qmatH(int l, CxH* Q){
    int d=2*l+1;
    for(int i=0;i<d*d;i++){ Q[i].re=0; Q[i].im=0; }
    double s2 = 1.0/sqrt(2.0);
    for(int m=-l;m<0;m++){
        Q[(l+m)*d + (l-m)].re = s2;
        Q[(l+m)*d + (l+m)].im = -s2;
    }
    Q[l*d+l].re = 1.0;
    for(int m=1;m<=l;m++){
        double sg = (m&1)? -1.0 : 1.0;
        Q[(l+m)*d + (l+m)].re = sg*s2;
        Q[(l+m)*d + (l-m)].im = sg*s2;
    }
    CxH f;
    int lm = l & 3;
    if (lm==0){f.re=1;f.im=0;} else if(lm==1){f.re=0;f.im=-1;}
    else if(lm==2){f.re=-1;f.im=0;} else {f.re=0;f.im=1;}
    for(int i=0;i<d*d;i++) Q[i]=cxmulH(Q[i],f);
}

static void real_cg_host(int l1,int l2,int l3, float* out){
    int d1=2*l1+1, d2=2*l2+1, d3=2*l3+1;
    double C[45];
    for(int i=0;i<d1*d2*d3;i++) C[i]=0.0;
    for(int m1=-l1;m1<=l1;m1++) for(int m2=-l2;m2<=l2;m2++){
        int m3=m1+m2; if (m3<-l3 || m3>l3) continue;
        double pref = sqrt((2*l3+1)*dfactH(l1+l2-l3)*dfactH(l1-l2+l3)*dfactH(-l1+l2+l3)/dfactH(l1+l2+l3+1));
        pref *= sqrt(dfactH(l1+m1)*dfactH(l1-m1)*dfactH(l2+m2)*dfactH(l2-m2)*dfactH(l3+m3)*dfactH(l3-m3));
        int kmin=0; if (l2-l3-m1>kmin) kmin=l2-l3-m1; if (l1-l3+m2>kmin) kmin=l1-l3+m2;
        int kmax=l1+l2-l3; if (l1-m1<kmax) kmax=l1-m1; if (l2+m2<kmax) kmax=l2+m2;
        double s=0.0;
        for(int k=kmin;k<=kmax;k++){
            double den = dfactH(k)*dfactH(l1+l2-l3-k)*dfactH(l1-m1-k)*dfactH(l2+m2-k)
                       * dfactH(l3-l2+m1+k)*dfactH(l3-l1-m2+k);
            s += ((k&1)? -1.0 : 1.0)/den;
        }
        C[((l1+m1)*d2 + (l2+m2))*d3 + (l3+m3)] = pref*s;
    }
    CxH Q1[25],Q2[25],Q3[25];
    qmatH(l1,Q1); qmatH(l2,Q2); qmatH(l3,Q3);
    double R[45]; double nrm=0.0;
    for(int j=0;j<d1;j++) for(int lI=0;lI<d2;lI++) for(int m=0;m<d3;m++){
        CxH acc; acc.re=0; acc.im=0;
        for(int i=0;i<d1;i++) for(int k=0;k<d2;k++){
            CxH q12 = cxmulH(Q1[i*d1+j], Q2[k*d2+lI]);
            for(int n=0;n<d3;n++){
                double c = C[(i*d2+k)*d3+n];
                if (c==0.0) continue;
                CxH q3c = Q3[n*d3+m]; q3c.im = -q3c.im;
                CxH t = cxmulH(q12, q3c);
                acc.re += t.re*c; acc.im += t.im*c;
            }
        }
        R[(j*d2+lI)*d3+m] = acc.re;
        nrm += acc.re*acc.re;
    }
    double inv = 1.0/sqrt(nrm);
    for(int i=0;i<d1*d2*d3;i++) out[i] = (float)(R[i]*inv);
}

// ---------------- cooperative shared-mid precompute (once per p) ----------------
// sMid u64 layout: [(v*JP + g)*32 + pj] pairs -> u64 idx ((v*JP+g)*32+pj)*2 + s
// holds m[2g+s]; JP = ceil(DJ/2)
template<int I2>
__device__ __forceinline__ void compute_mid_sh(
    const float* __restrict__ sXSp,
    const float* __restrict__ sXDp,
    u64* __restrict__ sMidU,
    const u64* __restrict__ sCG2,
    int tid)
{
    constexpr int DJ  = H_MID_DJ[I2];
    constexpr int JP  = (DJ+1)>>1;
    constexpr int J1  = H_T1_I1[I2];
    constexpr int J2  = H_T1_I2[I2];
    constexpr int D1  = J1 ? 3 : 1;
    constexpr int D2  = J2 ? 3 : 1;
    constexpr int CGO1= H_T1_CG[I2];
    for (int i=tid; i<16*DJ*32; i+=NTHREADS){
        int v  = i/(DJ*32);
        int r  = i - v*DJ*32;
        int j  = r >> 5;
        int pj = r & 31;
        int a = v>>2, b = v&3;
        u64 m = 0ull;
        #pragma unroll
        for (int ii=0; ii<D1; ii++){
            u64 xa = *(const u64*)(sXSp + ((J1 ? (4+a*3+ii) : a)<<6) + pj*2);
            #pragma unroll
            for (int kk=0; kk<D2; kk++){
                u64 xb = *(const u64*)(sXDp + ((J2 ? (4+b*3+kk) : b)<<6) + pj*2);
                fma2(m, mul2(xa, xb), sCG2[CGO1 + (ii*D2+kk)*DJ + j]);
            }
        }
        sMidU[((v*JP + (j>>1))*32 + pj)*2 + (j&1)] = m;
    }
}

// ---------------- z-contraction (independent of w0 / lane parity) ----------------
template<int P>
__device__ __forceinline__ void compute_z(
    int u, int v, int pj,
    const float* __restrict__ sXSp,
    const u64*  __restrict__ sMidU,
    const u64*  __restrict__ sCG2,
    u64 &z0, u64 &z1, u64 &z2)
{
    constexpr int I1  = HP_I1[P];
    constexpr int I2  = HP_I2[P];
    constexpr int IO  = HP_IO[P];
    constexpr int CGO2= HP_CG[P];
    constexpr int DJ  = H_MID_DJ[I2];
    constexpr int JP  = (DJ+1)>>1;
    constexpr int DI  = I1 ? 3 : 1;
    constexpr float PWT = H_T1_PW[I2]*HP_PW[P];

    u64 m[DJ];
    #pragma unroll
    for (int g=0; g<(DJ>>1); g++){
        ulonglong2 mm = *(const ulonglong2*)(sMidU + (v*JP+g)*64 + pj*2);
        m[2*g]   = mm.x;
        m[2*g+1] = mm.y;
    }
    if constexpr (DJ & 1)
        m[DJ-1] = sMidU[(v*JP + (DJ>>1))*64 + pj*2];

    z0=0ull; z1=0ull; z2=0ull;
    #pragma unroll
    for (int ii=0; ii<DI; ii++){
        u64 xu = *(const u64*)(sXSp + ((I1 ? (4+u*3+ii) : u)<<6) + pj*2);
        #pragma unroll
        for (int jj=0; jj<DJ; jj++){
            u64 t = mul2(xu, m[jj]);
            if constexpr (IO==1){
                fma2(z0, t, sCG2[CGO2 + (ii*DJ+jj)*3 + 0]);
                fma2(z1, t, sCG2[CGO2 + (ii*DJ+jj)*3 + 1]);
                fma2(z2, t, sCG2[CGO2 + (ii*DJ+jj)*3 + 2]);
            } else {
                fma2(z0, t, sCG2[CGO2 + ii*DJ+jj]);
            }
        }
    }
    const u64 pw2 = dup2(PWT);
    z0 = mul2(z0, pw2);
    if constexpr (IO==1){ z1 = mul2(z1, pw2); z2 = mul2(z2, pw2); }
}

template<int P>
__device__ __forceinline__ void apply_z(
    int w0, u64 y0, u64 y1, u64 z0, u64 z1, u64 z2, u64 (&outP)[16])
{
    constexpr int IO = HP_IO[P];
    if constexpr (IO==0){
        fma2(outP[w0],   y0, z0);
        fma2(outP[w0+1], y1, z0);
    } else {
        fma2(outP[4+3*w0+0], y0, z0);
        fma2(outP[4+3*w0+1], y0, z1);
        fma2(outP[4+3*w0+2], y0, z2);
        fma2(outP[4+3*(w0+1)+0], y1, z0);
        fma2(outP[4+3*(w0+1)+1], y1, z1);
        fma2(outP[4+3*(w0+1)+2], y1, z2);
    }
}

// 8 n-tiles per warp; each lane computes z for its parity's 4 tiles, the
// partner lane (lq^1, same vbase/pj/nh) supplies the other 4 via shfl.
template<int P>
__device__ __forceinline__ void consume_all(
    int u, int vbase, int w0, int half, int pj,
    const float* __restrict__ sXSp,
    const u64*  __restrict__ sMidU,
    const u64*  __restrict__ sCG2,
    const float (&C)[8][4],
    u64 (&outP)[16])
{
    constexpr int IO = HP_IO[P];
    #pragma unroll
    for (int g=0; g<4; g++){
        // this lane computes z for nt = g*2 + half
        const int vA = (g*2 + half)*2 + vbase;
        u64 z0,z1,z2;
        compute_z<P>(u, vA, pj, sXSp, sMidU, sCG2, z0, z1, z2);
        u64 zB0 = __shfl_xor_sync(0xffffffffu, z0, 1);
        u64 zB1 = 0ull, zB2 = 0ull;
        if constexpr (IO==1){
            zB1 = __shfl_xor_sync(0xffffffffu, z1, 1);
            zB2 = __shfl_xor_sync(0xffffffffu, z2, 1);
        }
        // route: even-nt z and odd-nt z
        u64 zE0 = half ? zB0 : z0,  zO0 = half ? z0 : zB0;
        u64 zE1 = 0ull, zO1 = 0ull, zE2 = 0ull, zO2 = 0ull;
        if constexpr (IO==1){
            zE1 = half ? zB1 : z1;  zO1 = half ? z1 : zB1;
            zE2 = half ? zB2 : z2;  zO2 = half ? z2 : zB2;
        }
        apply_z<P>(w0, pk2(C[g*2  ][0],C[g*2  ][2]), pk2(C[g*2  ][1],C[g*2  ][3]),
                   zE0, zE1, zE2, outP);
        apply_z<P>(w0, pk2(C[g*2+1][0],C[g*2+1][2]), pk2(C[g*2+1][1],C[g*2+1][3]),
                   zO0, zO1, zO2, outP);
    }
}

// merged init: blocks [0,40) pack W1 (kp-interleaved); blocks [40,...) zero output
__global__ void init_kernel(float* out, int n, const float* __restrict__ W1g){
    __shared__ float tile[64][65];
    if (blockIdx.x < WN/64){
        int n0 = blockIdx.x * 64;
        for (int i=threadIdx.x; i<64*64; i+=256){
            int h = i>>6, c = i&63;
            tile[h][c] = W1g[(size_t)h*WN + n0 + c]*0.125f;
        }
        __syncthreads();
        for (int i=threadIdx.x; i<64*32; i+=256){
            int c = i>>5, s = i&31;             // s = physical slot
            int kb = s & 24, r = s & 7;
            int kp = kb + (r>>1) + ((r&1)<<2);  // logical kp
            g_W1p[(size_t)(n0+c)*32 + s] = split_pair(tile[2*kp][c], tile[2*kp+1][c]);
        }
    } else {
        int i = (blockIdx.x - WN/64)*256 + threadIdx.x;
        if (i < n) out[i] = 0.f;
    }
}

// ---------------- main fused conv kernel ----------------
extern "C" __global__ void __launch_bounds__(NTHREADS, 2)
conv_kernel(const float* __restrict__ node_pos,
            const float* __restrict__ edge_type,
            const float* __restrict__ W0g,
            const int*   __restrict__ esrc,
            const int*   __restrict__ edst,
            float* __restrict__ out,
            const __grid_constant__ ConvConsts cc)
{
    extern __shared__ float sm[];
    u64*   sHa  = (u64*)sm;               // [64 e][34] u64  = 2176 u64 (17408 B)
    u64*   sW1p = sHa + 2176;             // [128 c][34] u64 = 4352 u64 (34816 B)
    u64*   sMidU= sW1p + 4352;            // [16 v][3 JP][32 pj][2] u64 = 3072 (24576 B)
    float* sXSp = (float*)(sMidU + 3072); // [16 d][64] pair-packed  1024
    float* sXDp = sXSp + 1024;            //                         1024
    u64*   sCG2 = (u64*)(sXDp + 1024);    // [160] duplicated CG      (1280 B)
    int*   sSrc = (int*)(sCG2 + 160);     //                           64
    int*   sDst = sSrc + 64;              //                           64

    float* sETT = (float*)sW1p;           // [16 k][64 e] alias (1024), dead after hidden
    float* sW0  = (float*)sW1p + 1024;    // [16 i][64 h] alias (1024), dead after hidden

    const int tid  = threadIdx.x;
    const int wid  = tid >> 5;
    const int lane = tid & 31;
    const int lj   = lane >> 2;   // 0..7
    const int lq   = lane & 3;    // 0..3
    const int mt   = wid >> 1;    // 0..3  (edge tile: rows mt*16..mt*16+15)
    const int nh   = wid & 1;     // 0..1  (column half of the 128-col chunk)
    const int pj   = mt*8 + lj;   // edge-pair index: (mt*16+lj, mt*16+lj+8)
    const int e0   = blockIdx.x * TB_E;

    for (int i=tid;i<160;i+=NTHREADS) sCG2[i]=dup2(cc.cg[i]);
    if (tid < 64){ sSrc[tid]=esrc[e0+tid]; sDst[tid]=edst[e0+tid]; }
    __syncthreads();

    // gather node features (pair-packed) + edge types transposed
    {
        int e=tid>>2, q=tid&3;
        float4 xs = ((const float4*)(node_pos + (size_t)sSrc[e]*16))[q];
        float4 xd = ((const float4*)(node_pos + (size_t)sDst[e]*16))[q];
        float4 t  = ((const float4*)(edge_type + (size_t)(e0+e)*16))[q];
        int j    = ((e>>4)<<3) | (e&7);    // pair index 0..31
        int half = (e>>3)&1;
        int base = j*2 + half;
        sXSp[(4*q+0)*64 + base] = xs.x;  sXSp[(4*q+1)*64 + base] = xs.y;
        sXSp[(4*q+2)*64 + base] = xs.z;  sXSp[(4*q+3)*64 + base] = xs.w;
        sXDp[(4*q+0)*64 + base] = xd.x;  sXDp[(4*q+1)*64 + base] = xd.y;
        sXDp[(4*q+2)*64 + base] = xd.z;  sXDp[(4*q+3)*64 + base] = xd.w;
        sETT[(4*q+0)*64 + e] = t.x;   sETT[(4*q+1)*64 + e] = t.y;
        sETT[(4*q+2)*64 + e] = t.z;   sETT[(4*q+3)*64 + e] = t.w;
    }
    for (int i=tid;i<16*64;i+=NTHREADS) sW0[i] = W0g[i]*0.25f;
    __syncthreads();

    // hidden: two adjacent H values per iteration, packed bf16 hi/lo pairs,
    // stored kp-INTERLEAVED: phys = kb + 2*(kp&3) + ((kp&7)>>2)
    for (int i=tid;i<TB_E*32;i+=NTHREADS){
        int kp=i&31, e=i>>5;
        int h0 = kp*2;
        float acc0=0.f, acc1=0.f;
        #pragma unroll
        for (int k=0;k<16;k++){
            float et = sETT[k*64+e];
            acc0 += et*sW0[k*64+h0];
            acc1 += et*sW0[k*64+h0+1];
        }
        float v0 = cc.silu_c * acc0 / (1.f + expf(-acc0));
        float v1 = cc.silu_c * acc1 / (1.f + expf(-acc1));
        int kb = kp & 24, l = kp & 7;
        int phys = kb + ((l&3)<<1) + (l>>2);
        sHa[e*34 + phys] = split_pair(v0, v1);
    }
    __syncthreads();   // hidden reads of sETT/sW0 done; sW1p region now free

    // prologue: async-load chunk 0 (off the loop path)
    for (int i=tid;i<2048;i+=NTHREADS){
        int c=i>>4, q=i&15;
        cpasync16(sW1p + c*34 + q*2, g_W1p + (size_t)c*32 + q*2);
    }
    cpasync_commit();

    u64 outP[16];
    #pragma unroll
    for (int k=0;k<16;k++) outP[k]=0ull;

    const int vbase = lq>>1;
    const int half  = lq&1;
    const int w0    = half<<1;

    for (int chunk=0; chunk<NCHUNKS; chunk++){
        cpasync_wait0();
        __syncthreads();   // chunk's W1 visible; prev epilogue done (sMid safe)

        // recompute shared mid when p = chunk>>1 changes (every even chunk)
        if ((chunk & 1) == 0){
            switch (chunk >> 1){
                case 0: compute_mid_sh<HP_I2[0]>(sXSp, sXDp, sMidU, sCG2, tid); break;
                case 1: compute_mid_sh<HP_I2[1]>(sXSp, sXDp, sMidU, sCG2, tid); break;
                case 2: compute_mid_sh<HP_I2[2]>(sXSp, sXDp, sMidU, sCG2, tid); break;
                case 3: compute_mid_sh<HP_I2[3]>(sXSp, sXDp, sMidU, sCG2, tid); break;
                case 4: compute_mid_sh<HP_I2[4]>(sXSp, sXDp, sMidU, sCG2, tid); break;
                case 5: compute_mid_sh<HP_I2[5]>(sXSp, sXDp, sMidU, sCG2, tid); break;
                case 6: compute_mid_sh<HP_I2[6]>(sXSp, sXDp, sMidU, sCG2, tid); break;
                case 7: compute_mid_sh<HP_I2[7]>(sXSp, sXDp, sMidU, sCG2, tid); break;
                case 8: compute_mid_sh<HP_I2[8]>(sXSp, sXDp, sMidU, sCG2, tid); break;
                case 9: compute_mid_sh<HP_I2[9]>(sXSp, sXDp, sMidU, sCG2, tid); break;
            }
        }

        // ---- tensor-core GEMM: C[16e x 64n] per warp via bf16 x3 (LDS.128 frags) ----
        float C[8][4];
        #pragma unroll
        for (int nt=0;nt<8;nt++){
            C[nt][0]=0.f; C[nt][1]=0.f; C[nt][2]=0.f; C[nt][3]=0.f;
        }
        #pragma unroll
        for (int k16=0;k16<4;k16++){
            const int kb = k16*8;
            // interleaved: ld128 @ kb+2lq = logical (kb+lq, kb+lq+4)
            ulonglong2 Ar0 = *(const ulonglong2*)(sHa + (mt*16+lj  )*34 + kb + 2*lq);
            ulonglong2 Ar1 = *(const ulonglong2*)(sHa + (mt*16+lj+8)*34 + kb + 2*lq);
            uint32_t a0h,a0l,a1h,a1l,a2h,a2l,a3h,a3l;
            upku(Ar0.x,a0h,a0l); upku(Ar1.x,a1h,a1l);
            upku(Ar0.y,a2h,a2l); upku(Ar1.y,a3h,a3l);
            #pragma unroll
            for (int nt=0;nt<8;nt++){
                const int col = nh*64 + nt*8 + lj;
                ulonglong2 B = *(const ulonglong2*)(sW1p + col*34 + kb + 2*lq);
                uint32_t b0h,b0l,b1h,b1l;
                upku(B.x,b0h,b0l); upku(B.y,b1h,b1l);
                mma_bf16(C[nt], a0h,a1h,a2h,a3h, b0h,b1h);
                mma_bf16(C[nt], a0h,a1h,a2h,a3h, b0l,b1l);
                mma_bf16(C[nt], a0l,a1l,a2l,a3l, b0h,b1h);
            }
        }
        __syncthreads();   // GEMM reads of sW1p done; mid writes visible below

        // issue next chunk's W1 loads into the SAME buffer; the epilogue hides them
        if (chunk+1 < NCHUNKS){
            for (int i=tid;i<2048;i+=NTHREADS){
                int c=i>>4, q=i&15;
                cpasync16(sW1p + c*34 + q*2,
                          g_W1p + (size_t)((chunk+1)*128+c)*32 + q*2);
            }
            cpasync_commit();
        }

        // ---- specialized epilogue: p = chunk>>1 uniform; u = (chunk&1)*2 + nh ----
        const int u = ((chunk&1)<<1) | nh;
        switch (chunk >> 1){
            case 0: consume_all<0>(u, vbase, w0, half, pj, sXSp, sMidU, sCG2, C, outP); break;
            case 1: consume_all<1>(u, vbase, w0, half, pj, sXSp, sMidU, sCG2, C, outP); break;
            case 2: consume_all<2>(u, vbase, w0, half, pj, sXSp, sMidU, sCG2, C, outP); break;
            case 3: consume_all<3>(u, vbase, w0, half, pj, sXSp, sMidU, sCG2, C, outP); break;
            case 4: consume_all<4>(u, vbase, w0, half, pj, sXSp, sMidU, sCG2, C, outP); break;
            case 5: consume_all<5>(u, vbase, w0, half, pj, sXSp, sMidU, sCG2, C, outP); break;
            case 6: consume_all<6>(u, vbase, w0, half, pj, sXSp, sMidU, sCG2, C, outP); break;
            case 7: consume_all<7>(u, vbase, w0, half, pj, sXSp, sMidU, sCG2, C, outP); break;
            case 8: consume_all<8>(u, vbase, w0, half, pj, sXSp, sMidU, sCG2, C, outP); break;
            case 9: consume_all<9>(u, vbase, w0, half, pj, sXSp, sMidU, sCG2, C, outP); break;
        }
    }

    // ---- reduce across the 4 lq lanes (same pair, different n subsets) ----
    #pragma unroll
    for (int msk=1; msk<4; msk<<=1){
        #pragma unroll
        for (int k=0;k<16;k++){
            u64 o = __shfl_xor_sync(0xffffffffu, outP[k], msk);
            outP[k] = add2(outP[k], o);
        }
    }
    cpasync_wait0();                 // no outstanding groups after last chunk; cheap
    __syncthreads();                 // all reads of shared done
    float* sSCR = (float*)sW1p;      // [2 nh][64 e][16] = 2048 floats
    if (lq == 0){
        int r1 = mt*16 + lj;
        #pragma unroll
        for (int k=0;k<16;k++){
            float lo,hi; upk2(outP[k], lo, hi);
            sSCR[(nh*64 + r1  )*16 + k] = lo;
            sSCR[(nh*64 + r1+8)*16 + k] = hi;
        }
    }
    __syncthreads();
    {
        int e  = tid >> 2;
        int dq = tid & 3;
        float4 v0 = *((float4*)(sSCR + e*16 + dq*4));
        float4 v1 = *((float4*)(sSCR + (64+e)*16 + dq*4));
        const float scale = 0.3535533905932738f; // 1/sqrt(NUM_NEIGHBORS=8)
        float* dst = out + (size_t)sDst[e]*16 + dq*4;
        atomicAdd(dst+0, (v0.x+v1.x)*scale);
        atomicAdd(dst+1, (v0.y+v1.y)*scale);
        atomicAdd(dst+2, (v0.z+v1.z)*scale);
        atomicAdd(dst+3, (v0.w+v1.w)*scale);
    }
}

// ---------------- launch ----------------
extern "C" void kernel_launch(void* const* d_in, const int* in_sizes, int n_in,
                              void* d_out, int out_size)
{
    const float* node_pos  = (const float*)d_in[0];
    const float* edge_type = (const float*)d_in[1];
    const float* W0        = (const float*)d_in[2];
    const float* W1        = (const float*)d_in[3];
    const int*   esrc      = (const int*)d_in[4];
    const int*   edst      = (const int*)d_in[5];
    float*       out       = (float*)d_out;

    ConvConsts cc;
    for (int i=0;i<160;i++) cc.cg[i]=0.f;
    real_cg_host(0,0,0, cc.cg+0);
    real_cg_host(0,1,1, cc.cg+1);
    real_cg_host(1,0,1, cc.cg+10);
    real_cg_host(1,1,0, cc.cg+19);
    real_cg_host(1,1,1, cc.cg+28);
    real_cg_host(1,1,2, cc.cg+55);
    real_cg_host(1,2,1, cc.cg+100);

    // SILU_C exactly as the reference computes it (200001-pt grid on [-12,12])
    double dx = 24.0/200000.0, s = 0.0;
    for (int i=0;i<=200000;i++){
        double x   = -12.0 + dx*(double)i;
        double phi = exp(-0.5*x*x)*0.3989422804014327;
        double sl  = x/(1.0+exp(-x));
        s += sl*sl*phi;
    }
    cc.silu_c = (float)(1.0/sqrt(s*dx));

    const int E = in_sizes[4];            // 65536
    const int nblocks = E / TB_E;         // 1024

    // bytes: sHa 17408 + sW1p 34816 + sMidU 24576 + sXSp 4096 + sXDp 4096
    //      + sCG2 1280 + 512 (idx) = 86784
    size_t smem = 86784;
    cudaFuncSetAttribute(conv_kernel, cudaFuncAttributeMaxDynamicSharedMemorySize, (int)smem);

    init_kernel<<<WN/64 + (out_size+255)/256, 256>>>(out, out_size, W1);
    conv_kernel<<<nblocks, NTHREADS, smem>>>(node_pos, edge_type, W0, esrc, edst, out, cc);
}

// round 17
// speedup vs baseline: 1.2193x; 1.2193x over previous
#include <cuda_runtime.h>
#include <math.h>
#include <stdint.h>

#define TB_E      64
#define NTHREADS  256
#define WN        2560
#define NCHUNKS   20

typedef unsigned long long u64;
typedef unsigned int u32;

// ---------------- compile-time path tables ----------------
constexpr int   H_MID_DJ[6]  = {1,3,3,1,3,5};
constexpr int   H_T1_I1[6] = {0,0,1,1,1,1};
constexpr int   H_T1_I2[6] = {0,1,0,1,1,1};
constexpr int   H_T1_CG[6] = {0,1,10,19,28,55};
constexpr float H_T1_PW[6] = {1.f,1.7320508075688772f,1.7320508075688772f,1.f,
                              1.7320508075688772f,2.2360679774997896f};
#define S1c 0.08838834764831845f /* sqrt(3/384) */
constexpr int   HP_I1[10] = {0,0,0,0,1,1,1,1,1,1};
constexpr int   HP_I2[10] = {0,1,2,3,0,1,2,3,4,5};
constexpr int   HP_IO[10] = {0,1,1,0,1,0,0,1,1,1};
constexpr int   HP_CG[10] = {0,1,1,0,10,19,19,10,28,100};
constexpr float HP_PW[10] = {0.0625f,S1c,S1c,0.0625f,S1c,0.0625f,0.0625f,S1c,S1c,S1c};

// CG table layout: [0]=C000(1), [1..9]=C011, [10..18]=C101, [19..27]=C110,
//                  [28..54]=C111, [55..99]=C112, [100..144]=C121
struct ConvConsts {
    float cg[160];
    float silu_c;
};

// pre-packed W1 planes (bf16x2 pairs), phys-interleaved slots:
// slot s in group of 8: logical kp-offset l = (s>>1) + 4*(s&1)
__device__ u32 g_W1hi[WN*32];
__device__ u32 g_W1lo[WN*32];

// ---------------- helpers ----------------
__device__ __forceinline__ u64 pk2(float lo, float hi){ u64 r; asm("mov.b64 %0,{%1,%2};" : "=l"(r) : "f"(lo), "f"(hi)); return r; }
__device__ __forceinline__ u64 dup2(float x){ u64 r; asm("mov.b64 %0,{%1,%1};" : "=l"(r) : "f"(x)); return r; }
__device__ __forceinline__ u64 mul2(u64 a, u64 b){ u64 r; asm("mul.rn.f32x2 %0,%1,%2;" : "=l"(r) : "l"(a), "l"(b)); return r; }
__device__ __forceinline__ void fma2(u64 &d, u64 a, u64 b){ asm("fma.rn.f32x2 %0,%1,%2,%0;" : "+l"(d) : "l"(a), "l"(b)); }
__device__ __forceinline__ u64 add2(u64 a, u64 b){ u64 r; asm("add.rn.f32x2 %0,%1,%2;" : "=l"(r) : "l"(a), "l"(b)); return r; }
__device__ __forceinline__ void upk2(u64 v, float &lo, float &hi){ asm("mov.b64 {%0,%1},%2;" : "=f"(lo), "=f"(hi) : "l"(v)); }

__device__ __forceinline__ void cpasync16(void* dst_smem, const void* src_gmem){
    uint32_t d = (uint32_t)__cvta_generic_to_shared(dst_smem);
    asm volatile("cp.async.cg.shared.global [%0], [%1], 16;" :: "r"(d), "l"(src_gmem) : "memory");
}
__device__ __forceinline__ void cpasync_commit(){ asm volatile("cp.async.commit_group;" ::: "memory"); }
__device__ __forceinline__ void cpasync_wait0(){ asm volatile("cp.async.wait_group 0;" ::: "memory"); }

// pack: low 16 = bf16(f0), high 16 = bf16(f1)
__device__ __forceinline__ uint32_t packbf(float f0, float f1){
    uint32_t r; asm("cvt.rn.bf16x2.f32 %0,%1,%2;" : "=r"(r) : "f"(f1), "f"(f0)); return r;
}
// split two floats into hi-pair and lo-pair u32s
__device__ __forceinline__ void split_pair2(float f0, float f1, u32 &hp, u32 &lp){
    hp = packbf(f0, f1);
    float h0 = __uint_as_float(hp << 16);
    float h1 = __uint_as_float(hp & 0xFFFF0000u);
    lp = packbf(f0 - h0, f1 - h1);
}

__device__ __forceinline__ void mma_bf16(float (&c)[4],
    uint32_t a0, uint32_t a1, uint32_t a2, uint32_t a3, uint32_t b0, uint32_t b1)
{
    asm("mma.sync.aligned.m16n8k16.row.col.f32.bf16.bf16.f32 "
        "{%0,%1,%2,%3},{%4,%5,%6,%7},{%8,%9},{%0,%1,%2,%3};"
        : "+f"(c[0]),"+f"(c[1]),"+f"(c[2]),"+f"(c[3])
        : "r"(a0),"r"(a1),"r"(a2),"r"(a3),"r"(b0),"r"(b1));
}

// ---------------- host-side CG computation (reference transliteration) ----------------
struct CxH { double re, im; };
static CxH cxmulH(CxH a, CxH b){ CxH r; r.re=a.re*b.re-a.im*b.im; r.im=a.re*b.im+a.im*b.re; return r; }
static double dfactH(int n){ double r=1.0; for(int i=2;i<=n;i++) r*=(double)i; return r; }

static void qmatH(int l, CxH* Q){
    int d=2*l+1;
    for(int i=0;i<d*d;i++){ Q[i].re=0; Q[i].im=0; }
    double s2 = 1.0/sqrt(2.0);
    for(int m=-l;m<0;m++){
        Q[(l+m)*d + (l-m)].re = s2;
        Q[(l+m)*d + (l+m)].im = -s2;
    }
    Q[l*d+l].re = 1.0;
    for(int m=1;m<=l;m++){
        double sg = (m&1)? -1.0 : 1.0;
        Q[(l+m)*d + (l+m)].re = sg*s2;
        Q[(l+m)*d + (l-m)].im = sg*s2;
    }
    CxH f;
    int lm = l & 3;
    if (lm==0){f.re=1;f.im=0;} else if(lm==1){f.re=0;f.im=-1;}
    else if(lm==2){f.re=-1;f.im=0;} else {f.re=0;f.im=1;}
    for(int i=0;i<d*d;i++) Q[i]=cxmulH(Q[i],f);
}

static void real_cg_host(int l1,int l2,int l3, float* out){
    int d1=2*l1+1, d2=2*l2+1, d3=2*l3+1;
    double C[45];
    for(int i=0;i<d1*d2*d3;i++) C[i]=0.0;
    for(int m1=-l1;m1<=l1;m1++) for(int m2=-l2;m2<=l2;m2++){
        int m3=m1+m2; if (m3<-l3 || m3>l3) continue;
        double pref = sqrt((2*l3+1)*dfactH(l1+l2-l3)*dfactH(l1-l2+l3)*dfactH(-l1+l2+l3)/dfactH(l1+l2+l3+1));
        pref *= sqrt(dfactH(l1+m1)*dfactH(l1-m1)*dfactH(l2+m2)*dfactH(l2-m2)*dfactH(l3+m3)*dfactH(l3-m3));
        int kmin=0; if (l2-l3-m1>kmin) kmin=l2-l3-m1; if (l1-l3+m2>kmin) kmin=l1-l3+m2;
        int kmax=l1+l2-l3; if (l1-m1<kmax) kmax=l1-m1; if (l2+m2<kmax) kmax=l2+m2;
        double s=0.0;
        for(int k=kmin;k<=kmax;k++){
            double den = dfactH(k)*dfactH(l1+l2-l3-k)*dfactH(l1-m1-k)*dfactH(l2+m2-k)
                       * dfactH(l3-l2+m1+k)*dfactH(l3-l1-m2+k);
            s += ((k&1)? -1.0 : 1.0)/den;
        }
        C[((l1+m1)*d2 + (l2+m2))*d3 + (l3+m3)] = pref*s;
    }
    CxH Q1[25],Q2[25],Q3[25];
    qmatH(l1,Q1); qmatH(l2,Q2); qmatH(l3,Q3);
    double R[45]; double nrm=0.0;
    for(int j=0;j<d1;j++) for(int lI=0;lI<d2;lI++) for(int m=0;m<d3;m++){
        CxH acc; acc.re=0; acc.im=0;
        for(int i=0;i<d1;i++) for(int k=0;k<d2;k++){
            CxH q12 = cxmulH(Q1[i*d1+j], Q2[k*d2+lI]);
            for(int n=0;n<d3;n++){
                double c = C[(i*d2+k)*d3+n];
                if (c==0.0) continue;
                CxH q3c = Q3[n*d3+m]; q3c.im = -q3c.im;
                CxH t = cxmulH(q12, q3c);
                acc.re += t.re*c; acc.im += t.im*c;
            }
        }
        R[(j*d2+lI)*d3+m] = acc.re;
        nrm += acc.re*acc.re;
    }
    double inv = 1.0/sqrt(nrm);
    for(int i=0;i<d1*d2*d3;i++) out[i] = (float)(R[i]*inv);
}

// ---------------- cooperative shared-mid precompute (once per p) ----------------
// sMid layout: [(v*DJ + j)][64 floats] pair-packed; u64 element at +pj*2
template<int I2>
__device__ __forceinline__ void compute_mid_sh(
    const float* __restrict__ sXSp,
    const float* __restrict__ sXDp,
    float* __restrict__ sMid,
    const u64* __restrict__ sCG2,
    int tid)
{
    constexpr int DJ  = H_MID_DJ[I2];
    constexpr int J1  = H_T1_I1[I2];
    constexpr int J2  = H_T1_I2[I2];
    constexpr int D1  = J1 ? 3 : 1;
    constexpr int D2  = J2 ? 3 : 1;
    constexpr int CGO1= H_T1_CG[I2];
    for (int i=tid; i<16*DJ*32; i+=NTHREADS){
        int v  = i/(DJ*32);
        int r  = i - v*DJ*32;
        int j  = r >> 5;
        int pj = r & 31;
        int a = v>>2, b = v&3;
        u64 m = 0ull;
        #pragma unroll
        for (int ii=0; ii<D1; ii++){
            u64 xa = *(const u64*)(sXSp + ((J1 ? (4+a*3+ii) : a)<<6) + pj*2);
            #pragma unroll
            for (int kk=0; kk<D2; kk++){
                u64 xb = *(const u64*)(sXDp + ((J2 ? (4+b*3+kk) : b)<<6) + pj*2);
                fma2(m, mul2(xa, xb), sCG2[CGO1 + (ii*D2+kk)*DJ + j]);
            }
        }
        *(u64*)(sMid + (v*DJ+j)*64 + pj*2) = m;
    }
}

// ---------------- z-contraction (xu hoisted; independent of lane parity) ----------------
template<int P>
__device__ __forceinline__ void compute_z(
    const u64* __restrict__ xu, int v, int pj,
    const float* __restrict__ sMid,
    const u64*  __restrict__ sCG2,
    u64 &z0, u64 &z1, u64 &z2)
{
    constexpr int I1  = HP_I1[P];
    constexpr int I2  = HP_I2[P];
    constexpr int IO  = HP_IO[P];
    constexpr int CGO2= HP_CG[P];
    constexpr int DJ  = H_MID_DJ[I2];
    constexpr int DI  = I1 ? 3 : 1;
    constexpr float PWT = H_T1_PW[I2]*HP_PW[P];

    u64 m[DJ];
    #pragma unroll
    for (int jj=0; jj<DJ; jj++)
        m[jj] = *(const u64*)(sMid + (v*DJ+jj)*64 + pj*2);

    z0=0ull; z1=0ull; z2=0ull;
    #pragma unroll
    for (int ii=0; ii<DI; ii++){
        #pragma unroll
        for (int jj=0; jj<DJ; jj++){
            u64 t = mul2(xu[ii], m[jj]);
            if constexpr (IO==1){
                fma2(z0, t, sCG2[CGO2 + (ii*DJ+jj)*3 + 0]);
                fma2(z1, t, sCG2[CGO2 + (ii*DJ+jj)*3 + 1]);
                fma2(z2, t, sCG2[CGO2 + (ii*DJ+jj)*3 + 2]);
            } else {
                fma2(z0, t, sCG2[CGO2 + ii*DJ+jj]);
            }
        }
    }
    const u64 pw2 = dup2(PWT);
    z0 = mul2(z0, pw2);
    if constexpr (IO==1){ z1 = mul2(z1, pw2); z2 = mul2(z2, pw2); }
}

template<int P>
__device__ __forceinline__ void apply_z(
    int w0, u64 y0, u64 y1, u64 z0, u64 z1, u64 z2, u64 (&outP)[16])
{
    constexpr int IO = HP_IO[P];
    if constexpr (IO==0){
        fma2(outP[w0],   y0, z0);
        fma2(outP[w0+1], y1, z0);
    } else {
        fma2(outP[4+3*w0+0], y0, z0);
        fma2(outP[4+3*w0+1], y0, z1);
        fma2(outP[4+3*w0+2], y0, z2);
        fma2(outP[4+3*(w0+1)+0], y1, z0);
        fma2(outP[4+3*(w0+1)+1], y1, z1);
        fma2(outP[4+3*(w0+1)+2], y1, z2);
    }
}

// 8 n-tiles per warp; each lane computes z for its parity's 4 tiles, the
// partner lane (lq^1, same vbase/pj/nh) supplies the other 4 via shfl.
template<int P>
__device__ __forceinline__ void consume_all(
    int u, int vbase, int w0, int half, int pj,
    const float* __restrict__ sXSp,
    const float* __restrict__ sMid,
    const u64*  __restrict__ sCG2,
    const float (&C)[8][4],
    u64 (&outP)[16])
{
    constexpr int IO = HP_IO[P];
    constexpr int I1 = HP_I1[P];
    constexpr int DI = I1 ? 3 : 1;
    u64 xu[DI];
    #pragma unroll
    for (int ii=0; ii<DI; ii++)
        xu[ii] = *(const u64*)(sXSp + ((I1 ? (4+u*3+ii) : u)<<6) + pj*2);
    #pragma unroll
    for (int g=0; g<4; g++){
        // this lane computes z for nt = g*2 + half
        const int vA = (g*2 + half)*2 + vbase;
        u64 z0,z1,z2;
        compute_z<P>(xu, vA, pj, sMid, sCG2, z0, z1, z2);
        u64 zB0 = __shfl_xor_sync(0xffffffffu, z0, 1);
        u64 zB1 = 0ull, zB2 = 0ull;
        if constexpr (IO==1){
            zB1 = __shfl_xor_sync(0xffffffffu, z1, 1);
            zB2 = __shfl_xor_sync(0xffffffffu, z2, 1);
        }
        // route: even-nt z and odd-nt z
        u64 zE0 = half ? zB0 : z0,  zO0 = half ? z0 : zB0;
        u64 zE1 = 0ull, zO1 = 0ull, zE2 = 0ull, zO2 = 0ull;
        if constexpr (IO==1){
            zE1 = half ? zB1 : z1;  zO1 = half ? z1 : zB1;
            zE2 = half ? zB2 : z2;  zO2 = half ? z2 : zB2;
        }
        apply_z<P>(w0, pk2(C[g*2  ][0],C[g*2  ][2]), pk2(C[g*2  ][1],C[g*2  ][3]),
                   zE0, zE1, zE2, outP);
        apply_z<P>(w0, pk2(C[g*2+1][0],C[g*2+1][2]), pk2(C[g*2+1][1],C[g*2+1][3]),
                   zO0, zO1, zO2, outP);
    }
}

// merged init: blocks [0,40) pack W1 planes; blocks [40,...) zero output
__global__ void init_kernel(float* out, int n, const float* __restrict__ W1g){
    __shared__ float tile[64][65];
    if (blockIdx.x < WN/64){
        int n0 = blockIdx.x * 64;
        for (int i=threadIdx.x; i<64*64; i+=256){
            int h = i>>6, c = i&63;
            tile[h][c] = W1g[(size_t)h*WN + n0 + c]*0.125f;
        }
        __syncthreads();
        for (int i=threadIdx.x; i<64*32; i+=256){
            int c = i>>5, s = i&31;             // s = physical slot
            int kb = s & 24, r = s & 7;
            int kp = kb + (r>>1) + ((r&1)<<2);  // logical kp
            u32 hp, lp;
            split_pair2(tile[2*kp][c], tile[2*kp+1][c], hp, lp);
            g_W1hi[(size_t)(n0+c)*32 + s] = hp;
            g_W1lo[(size_t)(n0+c)*32 + s] = lp;
        }
    } else {
        int i = (blockIdx.x - WN/64)*256 + threadIdx.x;
        if (i < n) out[i] = 0.f;
    }
}

// ---------------- main fused conv kernel ----------------
extern "C" __global__ void __launch_bounds__(NTHREADS, 2)
conv_kernel(const float* __restrict__ node_pos,
            const float* __restrict__ edge_type,
            const float* __restrict__ W0g,
            const int*   __restrict__ esrc,
            const int*   __restrict__ edst,
            float* __restrict__ out,
            const __grid_constant__ ConvConsts cc)
{
    extern __shared__ float sm[];
    u32*   sHaHi = (u32*)sm;              // [64 e][40] u32 = 2560 (10240 B)
    u32*   sHaLo = sHaHi + 2560;          //                 2560 (10240 B)
    u32*   sW1Hi = sHaLo + 2560;          // [128 c][40] u32 = 5120 (20480 B)
    u32*   sW1Lo = sW1Hi + 5120;          //                 5120 (20480 B)
    float* sMid  = (float*)(sW1Lo + 5120);// [80][64] floats = 5120 (20480 B)
    float* sXSp  = sMid + 5120;           // [16 d][64] pair-packed  1024
    float* sXDp  = sXSp + 1024;           //                         1024
    u64*   sCG2  = (u64*)(sXDp + 1024);   // [160] duplicated CG      (1280 B)
    int*   sSrc  = (int*)(sCG2 + 160);    //                           64
    int*   sDst  = sSrc + 64;             //                           64

    float* sETT = (float*)sW1Hi;          // [16 k][64 e] alias (1024), dead after hidden
    float* sW0  = (float*)sW1Hi + 1024;   // [16 i][64 h] alias (1024), dead after hidden

    const int tid  = threadIdx.x;
    const int wid  = tid >> 5;
    const int lane = tid & 31;
    const int lj   = lane >> 2;   // 0..7
    const int lq   = lane & 3;    // 0..3
    const int mt   = wid >> 1;    // 0..3  (edge tile: rows mt*16..mt*16+15)
    const int nh   = wid & 1;     // 0..1  (column half of the 128-col chunk)
    const int pj   = mt*8 + lj;   // edge-pair index: (mt*16+lj, mt*16+lj+8)
    const int e0   = blockIdx.x * TB_E;

    for (int i=tid;i<160;i+=NTHREADS) sCG2[i]=dup2(cc.cg[i]);
    if (tid < 64){ sSrc[tid]=esrc[e0+tid]; sDst[tid]=edst[e0+tid]; }
    __syncthreads();

    // gather node features (pair-packed) + edge types transposed
    {
        int e=tid>>2, q=tid&3;
        float4 xs = ((const float4*)(node_pos + (size_t)sSrc[e]*16))[q];
        float4 xd = ((const float4*)(node_pos + (size_t)sDst[e]*16))[q];
        float4 t  = ((const float4*)(edge_type + (size_t)(e0+e)*16))[q];
        int j    = ((e>>4)<<3) | (e&7);    // pair index 0..31
        int half = (e>>3)&1;
        int base = j*2 + half;
        sXSp[(4*q+0)*64 + base] = xs.x;  sXSp[(4*q+1)*64 + base] = xs.y;
        sXSp[(4*q+2)*64 + base] = xs.z;  sXSp[(4*q+3)*64 + base] = xs.w;
        sXDp[(4*q+0)*64 + base] = xd.x;  sXDp[(4*q+1)*64 + base] = xd.y;
        sXDp[(4*q+2)*64 + base] = xd.z;  sXDp[(4*q+3)*64 + base] = xd.w;
        sETT[(4*q+0)*64 + e] = t.x;   sETT[(4*q+1)*64 + e] = t.y;
        sETT[(4*q+2)*64 + e] = t.z;   sETT[(4*q+3)*64 + e] = t.w;
    }
    for (int i=tid;i<16*64;i+=NTHREADS) sW0[i] = W0g[i]*0.25f;
    __syncthreads();

    // hidden: two adjacent H values per iteration, split to hi/lo planes,
    // phys-interleaved slots: phys = kb + 2*(l&3) + (l>>2)
    for (int i=tid;i<TB_E*32;i+=NTHREADS){
        int kp=i&31, e=i>>5;
        int h0 = kp*2;
        float acc0=0.f, acc1=0.f;
        #pragma unroll
        for (int k=0;k<16;k++){
            float et = sETT[k*64+e];
            acc0 += et*sW0[k*64+h0];
            acc1 += et*sW0[k*64+h0+1];
        }
        float v0 = cc.silu_c * acc0 / (1.f + expf(-acc0));
        float v1 = cc.silu_c * acc1 / (1.f + expf(-acc1));
        u32 hp, lp;
        split_pair2(v0, v1, hp, lp);
        int kb = kp & 24, l = kp & 7;
        int phys = kb + ((l&3)<<1) + (l>>2);
        sHaHi[e*40 + phys] = hp;
        sHaLo[e*40 + phys] = lp;
    }
    __syncthreads();   // hidden reads of sETT/sW0 done; sW1 planes now free

    // prologue: async-load chunk 0 planes (off the loop path)
    for (int i=tid;i<1024;i+=NTHREADS){
        int c=i>>3, q=i&7;
        cpasync16(sW1Hi + c*40 + q*4, g_W1hi + (size_t)c*32 + q*4);
        cpasync16(sW1Lo + c*40 + q*4, g_W1lo + (size_t)c*32 + q*4);
    }
    cpasync_commit();

    u64 outP[16];
    #pragma unroll
    for (int k=0;k<16;k++) outP[k]=0ull;

    const int vbase = lq>>1;
    const int half  = lq&1;
    const int w0    = half<<1;

    for (int chunk=0; chunk<NCHUNKS; chunk++){
        cpasync_wait0();
        __syncthreads();   // chunk's W1 visible; prev epilogue done (sMid safe)

        // recompute shared mid when p = chunk>>1 changes (every even chunk)
        if ((chunk & 1) == 0){
            switch (chunk >> 1){
                case 0: compute_mid_sh<HP_I2[0]>(sXSp, sXDp, sMid, sCG2, tid); break;
                case 1: compute_mid_sh<HP_I2[1]>(sXSp, sXDp, sMid, sCG2, tid); break;
                case 2: compute_mid_sh<HP_I2[2]>(sXSp, sXDp, sMid, sCG2, tid); break;
                case 3: compute_mid_sh<HP_I2[3]>(sXSp, sXDp, sMid, sCG2, tid); break;
                case 4: compute_mid_sh<HP_I2[4]>(sXSp, sXDp, sMid, sCG2, tid); break;
                case 5: compute_mid_sh<HP_I2[5]>(sXSp, sXDp, sMid, sCG2, tid); break;
                case 6: compute_mid_sh<HP_I2[6]>(sXSp, sXDp, sMid, sCG2, tid); break;
                case 7: compute_mid_sh<HP_I2[7]>(sXSp, sXDp, sMid, sCG2, tid); break;
                case 8: compute_mid_sh<HP_I2[8]>(sXSp, sXDp, sMid, sCG2, tid); break;
                case 9: compute_mid_sh<HP_I2[9]>(sXSp, sXDp, sMid, sCG2, tid); break;
            }
        }

        // ---- tensor-core GEMM: C[16e x 64n] per warp via bf16 x3 (plane loads) ----
        float C[8][4];
        #pragma unroll
        for (int nt=0;nt<8;nt++){
            C[nt][0]=0.f; C[nt][1]=0.f; C[nt][2]=0.f; C[nt][3]=0.f;
        }
        #pragma unroll
        for (int k16=0;k16<4;k16++){
            const int kb = k16*8;
            const int ao = kb + 2*lq;
            // uint2 @ phys kb+2lq = logical (kb+lq, kb+lq+4): .x = a0, .y = a2
            uint2 Ah0 = *(const uint2*)(sHaHi + (mt*16+lj  )*40 + ao);
            uint2 Ah1 = *(const uint2*)(sHaHi + (mt*16+lj+8)*40 + ao);
            uint2 Al0 = *(const uint2*)(sHaLo + (mt*16+lj  )*40 + ao);
            uint2 Al1 = *(const uint2*)(sHaLo + (mt*16+lj+8)*40 + ao);
            #pragma unroll
            for (int nt=0;nt<8;nt++){
                const int col = nh*64 + nt*8 + lj;
                uint2 Bh = *(const uint2*)(sW1Hi + col*40 + ao);
                uint2 Bl = *(const uint2*)(sW1Lo + col*40 + ao);
                mma_bf16(C[nt], Ah0.x,Ah1.x,Ah0.y,Ah1.y, Bh.x,Bh.y);
                mma_bf16(C[nt], Ah0.x,Ah1.x,Ah0.y,Ah1.y, Bl.x,Bl.y);
                mma_bf16(C[nt], Al0.x,Al1.x,Al0.y,Al1.y, Bh.x,Bh.y);
            }
        }
        __syncthreads();   // GEMM reads of sW1 planes done; mid writes visible below

        // issue next chunk's W1 loads into the SAME buffers; epilogue hides them
        if (chunk+1 < NCHUNKS){
            for (int i=tid;i<1024;i+=NTHREADS){
                int c=i>>3, q=i&7;
                size_t src = (size_t)((chunk+1)*128+c)*32 + q*4;
                cpasync16(sW1Hi + c*40 + q*4, g_W1hi + src);
                cpasync16(sW1Lo + c*40 + q*4, g_W1lo + src);
            }
            cpasync_commit();
        }

        // ---- specialized epilogue: p = chunk>>1 uniform; u = (chunk&1)*2 + nh ----
        const int u = ((chunk&1)<<1) | nh;
        switch (chunk >> 1){
            case 0: consume_all<0>(u, vbase, w0, half, pj, sXSp, sMid, sCG2, C, outP); break;
            case 1: consume_all<1>(u, vbase, w0, half, pj, sXSp, sMid, sCG2, C, outP); break;
            case 2: consume_all<2>(u, vbase, w0, half, pj, sXSp, sMid, sCG2, C, outP); break;
            case 3: consume_all<3>(u, vbase, w0, half, pj, sXSp, sMid, sCG2, C, outP); break;
            case 4: consume_all<4>(u, vbase, w0, half, pj, sXSp, sMid, sCG2, C, outP); break;
            case 5: consume_all<5>(u, vbase, w0, half, pj, sXSp, sMid, sCG2, C, outP); break;
            case 6: consume_all<6>(u, vbase, w0, half, pj, sXSp, sMid, sCG2, C, outP); break;
            case 7: consume_all<7>(u, vbase, w0, half, pj, sXSp, sMid, sCG2, C, outP); break;
            case 8: consume_all<8>(u, vbase, w0, half, pj, sXSp, sMid, sCG2, C, outP); break;
            case 9: consume_all<9>(u, vbase, w0, half, pj, sXSp, sMid, sCG2, C, outP); break;
        }
    }

    // ---- reduce across the 4 lq lanes (same pair, different n subsets) ----
    #pragma unroll
    for (int msk=1; msk<4; msk<<=1){
        #pragma unroll
        for (int k=0;k<16;k++){
            u64 o = __shfl_xor_sync(0xffffffffu, outP[k], msk);
            outP[k] = add2(outP[k], o);
        }
    }
    cpasync_wait0();                 // no outstanding groups after last chunk; cheap
    __syncthreads();                 // all reads of shared done
    float* sSCR = (float*)sW1Hi;     // [2 nh][64 e][16] = 2048 floats
    if (lq == 0){
        int r1 = mt*16 + lj;
        #pragma unroll
        for (int k=0;k<16;k++){
            float lo,hi; upk2(outP[k], lo, hi);
            sSCR[(nh*64 + r1  )*16 + k] = lo;
            sSCR[(nh*64 + r1+8)*16 + k] = hi;
        }
    }
    __syncthreads();
    {
        int e  = tid >> 2;
        int dq = tid & 3;
        float4 v0 = *((float4*)(sSCR + e*16 + dq*4));
        float4 v1 = *((float4*)(sSCR + (64+e)*16 + dq*4));
        const float scale = 0.3535533905932738f; // 1/sqrt(NUM_NEIGHBORS=8)
        float* dst = out + (size_t)sDst[e]*16 + dq*4;
        atomicAdd(dst+0, (v0.x+v1.x)*scale);
        atomicAdd(dst+1, (v0.y+v1.y)*scale);
        atomicAdd(dst+2, (v0.z+v1.z)*scale);
        atomicAdd(dst+3, (v0.w+v1.w)*scale);
    }
}

// ---------------- launch ----------------
extern "C" void kernel_launch(void* const* d_in, const int* in_sizes, int n_in,
                              void* d_out, int out_size)
{
    const float* node_pos  = (const float*)d_in[0];
    const float* edge_type = (const float*)d_in[1];
    const float* W0        = (const float*)d_in[2];
    const float* W1        = (const float*)d_in[3];
    const int*   esrc      = (const int*)d_in[4];
    const int*   edst      = (const int*)d_in[5];
    float*       out       = (float*)d_out;

    ConvConsts cc;
    for (int i=0;i<160;i++) cc.cg[i]=0.f;
    real_cg_host(0,0,0, cc.cg+0);
    real_cg_host(0,1,1, cc.cg+1);
    real_cg_host(1,0,1, cc.cg+10);
    real_cg_host(1,1,0, cc.cg+19);
    real_cg_host(1,1,1, cc.cg+28);
    real_cg_host(1,1,2, cc.cg+55);
    real_cg_host(1,2,1, cc.cg+100);

    // SILU_C exactly as the reference computes it (200001-pt grid on [-12,12])
    double dx = 24.0/200000.0, s = 0.0;
    for (int i=0;i<=200000;i++){
        double x   = -12.0 + dx*(double)i;
        double phi = exp(-0.5*x*x)*0.3989422804014327;
        double sl  = x/(1.0+exp(-x));
        s += sl*sl*phi;
    }
    cc.silu_c = (float)(1.0/sqrt(s*dx));

    const int E = in_sizes[4];            // 65536
    const int nblocks = E / TB_E;         // 1024

    // bytes: sHa planes 20480 + sW1 planes 40960 + sMid 20480 + sXSp 4096
    //      + sXDp 4096 + sCG2 1280 + 512 (idx) = 91904
    size_t smem = 91904;
    cudaFuncSetAttribute(conv_kernel, cudaFuncAttributeMaxDynamicSharedMemorySize, (int)smem);

    init_kernel<<<WN/64 + (out_size+255)/256, 256>>>(out, out_size, W1);
    conv_kernel<<<nblocks, NTHREADS, smem>>>(node_pos, edge_type, W0, esrc, edst, out, cc);
}